// round 7
// baseline (speedup 1.0000x reference)
#include <cuda_runtime.h>
#include <cstdint>

// Problem constants
#define BATCH   4
#define HH      56
#define WW      56
#define EMBED   256
#define HEADS   8
#define HDIM    32
#define KS      7
#define K2      49
#define PAD     3
#define NPIX    (BATCH * HH * WW)      // 12544
#define SCALE   0.17677669529663687f   // 32^-0.5

// Scratch (device globals: allocation-free rule)
__device__ float g_qkv[(size_t)NPIX * 768];   // [pix][q(256) k(256) v(256)]
__device__ float g_att[(size_t)NPIX * 256];   // attention output, pre-projection

// ---------------------------------------------------------------------------
// Fused GEMM: Y[m, n] = A[m,:] . W_seg[n_in_seg,:] + bias_seg[n_in_seg]
// A: [M=12544, 256] row-major. Weights: [256,256] row-major (K contiguous).
// gridDim.x selects 128-wide column block; segment = 256 columns -> weight sel.
// BM=128, BN=128, BK=16, TM=TN=8, 256 threads.
// ---------------------------------------------------------------------------
__global__ __launch_bounds__(256)
void gemm_kernel(const float* __restrict__ A,
                 const float* __restrict__ w0, const float* __restrict__ w1,
                 const float* __restrict__ w2,
                 const float* __restrict__ b0, const float* __restrict__ b1,
                 const float* __restrict__ b2,
                 float* __restrict__ Y, int ldy)
{
    const int m0     = blockIdx.y * 128;
    const int nblk   = blockIdx.x;
    const int seg    = nblk >> 1;               // which 256-col segment
    const float* W    = (seg == 0) ? w0 : (seg == 1 ? w1 : w2);
    const float* bias = (seg == 0) ? b0 : (seg == 1 ? b1 : b2);
    const int nseg0  = (nblk & 1) * 128;        // column offset within segment
    const int nglob0 = nblk * 128;              // column offset in Y

    __shared__ float As[16][132];
    __shared__ float Bs[16][132];

    const int tid = threadIdx.x;
    const int txn = tid & 15;     // n direction
    const int tym = tid >> 4;     // m direction

    float acc[8][8];
#pragma unroll
    for (int i = 0; i < 8; i++)
#pragma unroll
        for (int j = 0; j < 8; j++) acc[i][j] = 0.0f;

    for (int k0 = 0; k0 < 256; k0 += 16) {
        // Load A tile (128x16) and W tile (128x16), both K-contiguous, transposed into smem.
#pragma unroll
        for (int r = 0; r < 2; r++) {
            int e   = tid + r * 256;
            int row = e >> 2;
            int kq  = (e & 3) * 4;
            float4 a = *(const float4*)(A + (size_t)(m0 + row) * 256 + k0 + kq);
            As[kq + 0][row] = a.x; As[kq + 1][row] = a.y;
            As[kq + 2][row] = a.z; As[kq + 3][row] = a.w;
            float4 b = *(const float4*)(W + (size_t)(nseg0 + row) * 256 + k0 + kq);
            Bs[kq + 0][row] = b.x; Bs[kq + 1][row] = b.y;
            Bs[kq + 2][row] = b.z; Bs[kq + 3][row] = b.w;
        }
        __syncthreads();

#pragma unroll
        for (int kk = 0; kk < 16; kk++) {
            float4 a0 = *(const float4*)&As[kk][tym * 4];
            float4 a1 = *(const float4*)&As[kk][64 + tym * 4];
            float4 q0 = *(const float4*)&Bs[kk][txn * 4];
            float4 q1 = *(const float4*)&Bs[kk][64 + txn * 4];
            float av[8] = {a0.x, a0.y, a0.z, a0.w, a1.x, a1.y, a1.z, a1.w};
            float bv[8] = {q0.x, q0.y, q0.z, q0.w, q1.x, q1.y, q1.z, q1.w};
#pragma unroll
            for (int i = 0; i < 8; i++)
#pragma unroll
                for (int j = 0; j < 8; j++)
                    acc[i][j] = fmaf(av[i], bv[j], acc[i][j]);
        }
        __syncthreads();
    }

    // Epilogue: add bias, write two float4 per row-fragment.
#pragma unroll
    for (int i = 0; i < 8; i++) {
        int row = m0 + ((i < 4) ? (tym * 4 + i) : (64 + tym * 4 + (i - 4)));
#pragma unroll
        for (int jq = 0; jq < 2; jq++) {
            int coln = (jq == 0) ? (txn * 4) : (64 + txn * 4);
            int jb   = jq * 4;
            float4 r;
            r.x = acc[i][jb + 0] + bias[nseg0 + coln + 0];
            r.y = acc[i][jb + 1] + bias[nseg0 + coln + 1];
            r.z = acc[i][jb + 2] + bias[nseg0 + coln + 2];
            r.w = acc[i][jb + 3] + bias[nseg0 + coln + 3];
            *(float4*)(Y + (size_t)row * ldy + nglob0 + coln) = r;
        }
    }
}

// ---------------------------------------------------------------------------
// Neighborhood attention. Block = one (batch, head, 8x8 pixel tile).
// k/v halo (14x14 pixels x 32 dims) staged in smem with stride-33 padding.
// Zero-padded out-of-bounds neighbors -> logit exactly 0, v exactly 0
// (faithful to F.unfold zero padding in the reference).
// ---------------------------------------------------------------------------
#define HALO   14
#define HPIX   (HALO * HALO)    // 196
#define SSTR   33               // padded float stride per halo pixel

__global__ __launch_bounds__(64)
void attn_kernel(const float* __restrict__ qkv, float* __restrict__ out)
{
    const int tx = threadIdx.x & 7;
    const int ty = threadIdx.x >> 3;
    const int tile_x0 = blockIdx.x * 8;
    const int tile_y0 = blockIdx.y * 8;
    const int bh = blockIdx.z;
    const int b  = bh >> 3;
    const int h  = bh & 7;
    const int base = b * (HH * WW);

    extern __shared__ float sm[];
    float* sk = sm;
    float* sv = sm + HPIX * SSTR;

    // ---- stage k/v halo ----
    for (int e = threadIdx.x; e < HPIX * 8; e += 64) {
        int hp = e >> 3;
        int f  = e & 7;
        int hy = hp / HALO;
        int hx = hp - hy * HALO;
        int gy = tile_y0 - PAD + hy;
        int gx = tile_x0 - PAD + hx;
        float4 kq = make_float4(0.f, 0.f, 0.f, 0.f);
        float4 vq = make_float4(0.f, 0.f, 0.f, 0.f);
        if ((unsigned)gy < (unsigned)HH && (unsigned)gx < (unsigned)WW) {
            const float* p = qkv + (size_t)(base + gy * WW + gx) * 768 + h * HDIM + f * 4;
            kq = *(const float4*)(p + 256);
            vq = *(const float4*)(p + 512);
        }
        float* skp = sk + hp * SSTR + f * 4;
        skp[0] = kq.x; skp[1] = kq.y; skp[2] = kq.z; skp[3] = kq.w;
        float* svp = sv + hp * SSTR + f * 4;
        svp[0] = vq.x; svp[1] = vq.y; svp[2] = vq.z; svp[3] = vq.w;
    }
    __syncthreads();

    const int gy  = tile_y0 + ty;
    const int gx  = tile_x0 + tx;
    const int pix = base + gy * WW + gx;

    // ---- load q (32 dims) ----
    float q[HDIM];
    {
        const float4* qp = (const float4*)(qkv + (size_t)pix * 768 + h * HDIM);
#pragma unroll
        for (int i = 0; i < 8; i++) {
            float4 t = qp[i];
            q[4 * i + 0] = t.x; q[4 * i + 1] = t.y;
            q[4 * i + 2] = t.z; q[4 * i + 3] = t.w;
        }
    }

    // ---- logits over 49 neighbors ----
    float lg[K2];
#pragma unroll
    for (int i = 0; i < KS; i++) {
#pragma unroll
        for (int j = 0; j < KS; j++) {
            const float* kp = sk + ((ty + i) * HALO + tx + j) * SSTR;
            float a = 0.0f;
#pragma unroll
            for (int d = 0; d < HDIM; d++) a = fmaf(q[d], kp[d], a);
            lg[i * KS + j] = a * SCALE;
        }
    }

    // ---- softmax (max-subtracted; OOB neighbors carry logit 0, included) ----
    float m = lg[0];
#pragma unroll
    for (int t = 1; t < K2; t++) m = fmaxf(m, lg[t]);
    float s = 0.0f;
#pragma unroll
    for (int t = 0; t < K2; t++) { lg[t] = __expf(lg[t] - m); s += lg[t]; }
    const float inv = 1.0f / s;

    // ---- weighted sum of v ----
    float o[HDIM];
#pragma unroll
    for (int d = 0; d < HDIM; d++) o[d] = 0.0f;
#pragma unroll
    for (int i = 0; i < KS; i++) {
#pragma unroll
        for (int j = 0; j < KS; j++) {
            const float* vp = sv + ((ty + i) * HALO + tx + j) * SSTR;
            const float p = lg[i * KS + j];
#pragma unroll
            for (int d = 0; d < HDIM; d++) o[d] = fmaf(p, vp[d], o[d]);
        }
    }

    float* op = out + (size_t)pix * 256 + h * HDIM;
#pragma unroll
    for (int i = 0; i < 8; i++) {
        float4 r = make_float4(o[4 * i + 0] * inv, o[4 * i + 1] * inv,
                               o[4 * i + 2] * inv, o[4 * i + 3] * inv);
        *(float4*)(op + 4 * i) = r;
    }
}

// ---------------------------------------------------------------------------
// kernel_launch
//
// INPUT ORDER FIX: setup_inputs() builds the dict in insertion order
//   x, wq, wk, wv, wo, bq, bk, bv, bo   (all weights, then all biases)
// NOT the reference() signature order. Bind accordingly. Deterministic
// runtime guard on in_sizes[2] (65536 vs 256) covers both serializations.
// ---------------------------------------------------------------------------
extern "C" void kernel_launch(void* const* d_in, const int* in_sizes, int n_in,
                              void* d_out, int out_size)
{
    const float* x;
    const float *wq, *wk, *wv, *wo;
    const float *bq, *bk, *bv, *bo;

    x = (const float*)d_in[0];
    if (in_sizes[2] == EMBED * EMBED) {
        // grouped order: x, wq, wk, wv, wo, bq, bk, bv, bo
        wq = (const float*)d_in[1];
        wk = (const float*)d_in[2];
        wv = (const float*)d_in[3];
        wo = (const float*)d_in[4];
        bq = (const float*)d_in[5];
        bk = (const float*)d_in[6];
        bv = (const float*)d_in[7];
        bo = (const float*)d_in[8];
    } else {
        // signature order: x, wq, bq, wk, bk, wv, bv, wo, bo
        wq = (const float*)d_in[1];
        bq = (const float*)d_in[2];
        wk = (const float*)d_in[3];
        bk = (const float*)d_in[4];
        wv = (const float*)d_in[5];
        bv = (const float*)d_in[6];
        wo = (const float*)d_in[7];
        bo = (const float*)d_in[8];
    }
    float* out = (float*)d_out;

    float* qkv = nullptr;
    float* att = nullptr;
    cudaGetSymbolAddress((void**)&qkv, g_qkv);
    cudaGetSymbolAddress((void**)&att, g_att);

    const int smem_attn = 2 * HPIX * SSTR * (int)sizeof(float);  // 51744 B
    cudaFuncSetAttribute(attn_kernel, cudaFuncAttributeMaxDynamicSharedMemorySize, smem_attn);

    // 1) fused QKV projection: [12544,256] x [768,256]^T -> g_qkv
    {
        dim3 grid(6, NPIX / 128);
        gemm_kernel<<<grid, 256>>>(x, wq, wk, wv, bq, bk, bv, qkv, 768);
    }

    // 2) neighborhood attention
    {
        dim3 grid(WW / 8, HH / 8, BATCH * HEADS);
        attn_kernel<<<grid, 64, smem_attn>>>(qkv, att);
    }

    // 3) output projection: [12544,256] x [256,256]^T -> out
    {
        dim3 grid(2, NPIX / 128);
        gemm_kernel<<<grid, 256>>>(att, wo, wo, wo, bo, bo, bo, out, 256);
    }
}

// round 9
// speedup vs baseline: 1.0008x; 1.0008x over previous
#include <cuda_runtime.h>
#include <cstdint>

// Problem constants
#define BATCH   4
#define HH      56
#define WW      56
#define EMBED   256
#define HEADS   8
#define HDIM    32
#define KS      7
#define K2      49
#define PAD     3
#define NPIX    (BATCH * HH * WW)      // 12544
#define SCALE   0.17677669529663687f   // 32^-0.5

// Scratch (device globals: allocation-free rule)
__device__ float g_qkv[(size_t)NPIX * 768];   // [pix][q(256) k(256) v(256)]
__device__ float g_att[(size_t)NPIX * 256];   // attention output, pre-projection

// ---------------------------------------------------------------------------
// Fused GEMM: Y[m, n] = A[m,:] . W_seg[n_in_seg,:] + bias_seg[n_in_seg]
// A: [M=12544, 256] row-major. Weights: [256,256] row-major (K contiguous).
// gridDim.x selects 128-wide column block; segment = 256 columns -> weight sel.
// BM=128, BN=128, BK=16, TM=TN=8, 256 threads.
// ---------------------------------------------------------------------------
__global__ __launch_bounds__(256)
void gemm_kernel(const float* __restrict__ A,
                 const float* __restrict__ w0, const float* __restrict__ w1,
                 const float* __restrict__ w2,
                 const float* __restrict__ b0, const float* __restrict__ b1,
                 const float* __restrict__ b2,
                 float* __restrict__ Y, int ldy)
{
    const int m0     = blockIdx.y * 128;
    const int nblk   = blockIdx.x;
    const int seg    = nblk >> 1;               // which 256-col segment
    const float* W    = (seg == 0) ? w0 : (seg == 1 ? w1 : w2);
    const float* bias = (seg == 0) ? b0 : (seg == 1 ? b1 : b2);
    const int nseg0  = (nblk & 1) * 128;        // column offset within segment
    const int nglob0 = nblk * 128;              // column offset in Y

    __shared__ float As[16][132];
    __shared__ float Bs[16][132];

    const int tid = threadIdx.x;
    const int txn = tid & 15;     // n direction
    const int tym = tid >> 4;     // m direction

    float acc[8][8];
#pragma unroll
    for (int i = 0; i < 8; i++)
#pragma unroll
        for (int j = 0; j < 8; j++) acc[i][j] = 0.0f;

    for (int k0 = 0; k0 < 256; k0 += 16) {
        // Load A tile (128x16) and W tile (128x16), both K-contiguous, transposed into smem.
#pragma unroll
        for (int r = 0; r < 2; r++) {
            int e   = tid + r * 256;
            int row = e >> 2;
            int kq  = (e & 3) * 4;
            float4 a = *(const float4*)(A + (size_t)(m0 + row) * 256 + k0 + kq);
            As[kq + 0][row] = a.x; As[kq + 1][row] = a.y;
            As[kq + 2][row] = a.z; As[kq + 3][row] = a.w;
            float4 b = *(const float4*)(W + (size_t)(nseg0 + row) * 256 + k0 + kq);
            Bs[kq + 0][row] = b.x; Bs[kq + 1][row] = b.y;
            Bs[kq + 2][row] = b.z; Bs[kq + 3][row] = b.w;
        }
        __syncthreads();

#pragma unroll
        for (int kk = 0; kk < 16; kk++) {
            float4 a0 = *(const float4*)&As[kk][tym * 4];
            float4 a1 = *(const float4*)&As[kk][64 + tym * 4];
            float4 q0 = *(const float4*)&Bs[kk][txn * 4];
            float4 q1 = *(const float4*)&Bs[kk][64 + txn * 4];
            float av[8] = {a0.x, a0.y, a0.z, a0.w, a1.x, a1.y, a1.z, a1.w};
            float bv[8] = {q0.x, q0.y, q0.z, q0.w, q1.x, q1.y, q1.z, q1.w};
#pragma unroll
            for (int i = 0; i < 8; i++)
#pragma unroll
                for (int j = 0; j < 8; j++)
                    acc[i][j] = fmaf(av[i], bv[j], acc[i][j]);
        }
        __syncthreads();
    }

    // Epilogue: add bias, write two float4 per row-fragment.
#pragma unroll
    for (int i = 0; i < 8; i++) {
        int row = m0 + ((i < 4) ? (tym * 4 + i) : (64 + tym * 4 + (i - 4)));
#pragma unroll
        for (int jq = 0; jq < 2; jq++) {
            int coln = (jq == 0) ? (txn * 4) : (64 + txn * 4);
            int jb   = jq * 4;
            float4 r;
            r.x = acc[i][jb + 0] + bias[nseg0 + coln + 0];
            r.y = acc[i][jb + 1] + bias[nseg0 + coln + 1];
            r.z = acc[i][jb + 2] + bias[nseg0 + coln + 2];
            r.w = acc[i][jb + 3] + bias[nseg0 + coln + 3];
            *(float4*)(Y + (size_t)row * ldy + nglob0 + coln) = r;
        }
    }
}

// ---------------------------------------------------------------------------
// Neighborhood attention. Block = one (batch, head, 8x8 pixel tile).
// k/v halo (14x14 pixels x 32 dims) staged in smem with stride-33 padding.
// Zero-padded out-of-bounds neighbors -> logit exactly 0, v exactly 0
// (faithful to F.unfold zero padding in the reference).
// ---------------------------------------------------------------------------
#define HALO   14
#define HPIX   (HALO * HALO)    // 196
#define SSTR   33               // padded float stride per halo pixel

__global__ __launch_bounds__(64)
void attn_kernel(const float* __restrict__ qkv, float* __restrict__ out)
{
    const int tx = threadIdx.x & 7;
    const int ty = threadIdx.x >> 3;
    const int tile_x0 = blockIdx.x * 8;
    const int tile_y0 = blockIdx.y * 8;
    const int bh = blockIdx.z;
    const int b  = bh >> 3;
    const int h  = bh & 7;
    const int base = b * (HH * WW);

    extern __shared__ float sm[];
    float* sk = sm;
    float* sv = sm + HPIX * SSTR;

    // ---- stage k/v halo ----
    for (int e = threadIdx.x; e < HPIX * 8; e += 64) {
        int hp = e >> 3;
        int f  = e & 7;
        int hy = hp / HALO;
        int hx = hp - hy * HALO;
        int gy = tile_y0 - PAD + hy;
        int gx = tile_x0 - PAD + hx;
        float4 kq = make_float4(0.f, 0.f, 0.f, 0.f);
        float4 vq = make_float4(0.f, 0.f, 0.f, 0.f);
        if ((unsigned)gy < (unsigned)HH && (unsigned)gx < (unsigned)WW) {
            const float* p = qkv + (size_t)(base + gy * WW + gx) * 768 + h * HDIM + f * 4;
            kq = *(const float4*)(p + 256);
            vq = *(const float4*)(p + 512);
        }
        float* skp = sk + hp * SSTR + f * 4;
        skp[0] = kq.x; skp[1] = kq.y; skp[2] = kq.z; skp[3] = kq.w;
        float* svp = sv + hp * SSTR + f * 4;
        svp[0] = vq.x; svp[1] = vq.y; svp[2] = vq.z; svp[3] = vq.w;
    }
    __syncthreads();

    const int gy  = tile_y0 + ty;
    const int gx  = tile_x0 + tx;
    const int pix = base + gy * WW + gx;

    // ---- load q (32 dims) ----
    float q[HDIM];
    {
        const float4* qp = (const float4*)(qkv + (size_t)pix * 768 + h * HDIM);
#pragma unroll
        for (int i = 0; i < 8; i++) {
            float4 t = qp[i];
            q[4 * i + 0] = t.x; q[4 * i + 1] = t.y;
            q[4 * i + 2] = t.z; q[4 * i + 3] = t.w;
        }
    }

    // ---- logits over 49 neighbors ----
    float lg[K2];
#pragma unroll
    for (int i = 0; i < KS; i++) {
#pragma unroll
        for (int j = 0; j < KS; j++) {
            const float* kp = sk + ((ty + i) * HALO + tx + j) * SSTR;
            float a = 0.0f;
#pragma unroll
            for (int d = 0; d < HDIM; d++) a = fmaf(q[d], kp[d], a);
            lg[i * KS + j] = a * SCALE;
        }
    }

    // ---- softmax (max-subtracted; OOB neighbors carry logit 0, included) ----
    float m = lg[0];
#pragma unroll
    for (int t = 1; t < K2; t++) m = fmaxf(m, lg[t]);
    float s = 0.0f;
#pragma unroll
    for (int t = 0; t < K2; t++) { lg[t] = __expf(lg[t] - m); s += lg[t]; }
    const float inv = 1.0f / s;

    // ---- weighted sum of v ----
    float o[HDIM];
#pragma unroll
    for (int d = 0; d < HDIM; d++) o[d] = 0.0f;
#pragma unroll
    for (int i = 0; i < KS; i++) {
#pragma unroll
        for (int j = 0; j < KS; j++) {
            const float* vp = sv + ((ty + i) * HALO + tx + j) * SSTR;
            const float p = lg[i * KS + j];
#pragma unroll
            for (int d = 0; d < HDIM; d++) o[d] = fmaf(p, vp[d], o[d]);
        }
    }

    float* op = out + (size_t)pix * 256 + h * HDIM;
#pragma unroll
    for (int i = 0; i < 8; i++) {
        float4 r = make_float4(o[4 * i + 0] * inv, o[4 * i + 1] * inv,
                               o[4 * i + 2] * inv, o[4 * i + 3] * inv);
        *(float4*)(op + 4 * i) = r;
    }
}

// ---------------------------------------------------------------------------
// kernel_launch
//
// INPUT ORDER FIX: setup_inputs() builds the dict in insertion order
//   x, wq, wk, wv, wo, bq, bk, bv, bo   (all weights, then all biases)
// NOT the reference() signature order. Bind accordingly. Deterministic
// runtime guard on in_sizes[2] (65536 vs 256) covers both serializations.
// ---------------------------------------------------------------------------
extern "C" void kernel_launch(void* const* d_in, const int* in_sizes, int n_in,
                              void* d_out, int out_size)
{
    const float* x;
    const float *wq, *wk, *wv, *wo;
    const float *bq, *bk, *bv, *bo;

    x = (const float*)d_in[0];
    if (in_sizes[2] == EMBED * EMBED) {
        // grouped order: x, wq, wk, wv, wo, bq, bk, bv, bo
        wq = (const float*)d_in[1];
        wk = (const float*)d_in[2];
        wv = (const float*)d_in[3];
        wo = (const float*)d_in[4];
        bq = (const float*)d_in[5];
        bk = (const float*)d_in[6];
        bv = (const float*)d_in[7];
        bo = (const float*)d_in[8];
    } else {
        // signature order: x, wq, bq, wk, bk, wv, bv, wo, bo
        wq = (const float*)d_in[1];
        bq = (const float*)d_in[2];
        wk = (const float*)d_in[3];
        bk = (const float*)d_in[4];
        wv = (const float*)d_in[5];
        bv = (const float*)d_in[6];
        wo = (const float*)d_in[7];
        bo = (const float*)d_in[8];
    }
    float* out = (float*)d_out;

    float* qkv = nullptr;
    float* att = nullptr;
    cudaGetSymbolAddress((void**)&qkv, g_qkv);
    cudaGetSymbolAddress((void**)&att, g_att);

    const int smem_attn = 2 * HPIX * SSTR * (int)sizeof(float);  // 51744 B
    cudaFuncSetAttribute(attn_kernel, cudaFuncAttributeMaxDynamicSharedMemorySize, smem_attn);

    // 1) fused QKV projection: [12544,256] x [768,256]^T -> g_qkv
    {
        dim3 grid(6, NPIX / 128);
        gemm_kernel<<<grid, 256>>>(x, wq, wk, wv, bq, bk, bv, qkv, 768);
    }

    // 2) neighborhood attention
    {
        dim3 grid(WW / 8, HH / 8, BATCH * HEADS);
        attn_kernel<<<grid, 64, smem_attn>>>(qkv, att);
    }

    // 3) output projection: [12544,256] x [256,256]^T -> out
    {
        dim3 grid(2, NPIX / 128);
        gemm_kernel<<<grid, 256>>>(att, wo, wo, wo, bo, bo, bo, out, 256);
    }
}